// round 17
// baseline (speedup 1.0000x reference)
#include <cuda_runtime.h>
#include <cuda_bf16.h>
#include <cuda_fp16.h>

#define BB 8
#define NN 1024
#define DIN 512
#define HH 8
#define INNER 512
#define DOUT 512
#define NROWS (BB*NN)            // 8192
#define SCALE 0.125f
#define LOG2E 1.4426950408889634f
#define QKCOLS 1024              // q|k halves per row
#define QKV_COLS 1536

// ---- scratch (device globals; no runtime allocation) ----
__device__ __half g_qk[(size_t)NROWS * QKCOLS];             // q|k fp16
__device__ __half g_vTh[(size_t)BB * HH * 64 * NN];         // V^T fp16 per (b,h): [d][token]
__device__ __half g_bias_h[(size_t)BB * HH * NN * NN];      // bias transposed+masked fp16, 128MB
__device__ __half g_attf[(size_t)NROWS * INNER];            // attention out fp16 [row][hd]
__device__ __half g_woutf[(size_t)DOUT * INNER];            // Wout fp16 n-major [n][k]
__device__ __half g_xf[(size_t)NROWS * DIN];                // x fp16 [row][k]
__device__ unsigned g_wqh[(size_t)QKV_COLS * 256];          // [SCALE*Wq|Wkv] fp16-hi pairs n-major
__device__ unsigned g_wql[(size_t)QKV_COLS * 256];          // fp16-lo pairs (subnormal residual)
__device__ unsigned char g_maskb[BB * NN];

// ---- helpers ----
__device__ __forceinline__ float ex2(float x) {
    float y;
    asm("ex2.approx.ftz.f32 %0, %1;" : "=f"(y) : "f"(x));
    return y;
}
__device__ __forceinline__ unsigned h2ex2(unsigned a) {
    unsigned d;
    asm("ex2.approx.f16x2 %0, %1;" : "=r"(d) : "r"(a));
    return d;
}
// pack two f32 into f16x2: low half = lo, high half = hi
__device__ __forceinline__ unsigned pack_h2(float lo, float hi) {
    unsigned d;
    asm("cvt.rn.f16x2.f32 %0, %1, %2;" : "=r"(d) : "f"(hi), "f"(lo));
    return d;
}
__device__ __forceinline__ void cp16(void* sp, const void* gp) {
    unsigned s = (unsigned)__cvta_generic_to_shared(sp);
    asm volatile("cp.async.cg.shared.global [%0], [%1], 16;\n" :: "r"(s), "l"(gp));
}
#define CP_COMMIT asm volatile("cp.async.commit_group;\n")
#define CP_WAIT0  asm volatile("cp.async.wait_group 0;\n")
#define CP_WAIT1  asm volatile("cp.async.wait_group 1;\n")

__device__ __forceinline__ void ldsm4(unsigned& r0, unsigned& r1, unsigned& r2, unsigned& r3,
                                      unsigned saddr) {
    asm volatile("ldmatrix.sync.aligned.m8n8.x4.shared.b16 {%0,%1,%2,%3}, [%4];"
                 : "=r"(r0), "=r"(r1), "=r"(r2), "=r"(r3) : "r"(saddr));
}
__device__ __forceinline__ void mma16f(float& c0, float& c1, float& c2, float& c3,
                                       unsigned a0, unsigned a1, unsigned a2, unsigned a3,
                                       unsigned b0, unsigned b1) {
    asm volatile(
        "mma.sync.aligned.m16n8k16.row.col.f32.f16.f16.f32 "
        "{%0,%1,%2,%3},{%4,%5,%6,%7},{%8,%9},{%0,%1,%2,%3};\n"
        : "+f"(c0), "+f"(c1), "+f"(c2), "+f"(c3)
        : "r"(a0), "r"(a1), "r"(a2), "r"(a3), "r"(b0), "r"(b1));
}

// =====================================================================
// k_prep (compact): [CTA 0] mask; [1..1024] x -> fp16; [1025..1280] weights
// =====================================================================
__global__ __launch_bounds__(256) void k_prep(const unsigned char* __restrict__ m,
                                              const float* __restrict__ x,
                                              const float* __restrict__ Wq,
                                              const float* __restrict__ Wkv,
                                              const float* __restrict__ Wout) {
    const int bid = blockIdx.x;
    if (bid == 0) {
        __shared__ int s_notI32, s_notF32;
        if (threadIdx.x == 0) { s_notI32 = 0; s_notF32 = 0; }
        __syncthreads();
        const unsigned* mw = (const unsigned*)m;
        int notI = 0, notF = 0;
        for (int i = threadIdx.x; i < BB * NN / 4; i += 256) {
            unsigned w = mw[i];
            if (w & 0xFFFFFF00u) notI = 1;
            if (w != 0u && w != 0x3F800000u) notF = 1;
        }
        if (notI) atomicOr(&s_notI32, 1);
        if (notF) atomicOr(&s_notF32, 1);
        __syncthreads();
        const int notI32 = s_notI32, notF32 = s_notF32;
        for (int i = threadIdx.x; i < BB * NN; i += 256) {
            unsigned char v;
            if (!notF32)      v = (((const unsigned*)m)[i] != 0u) ? 1 : 0;
            else if (!notI32) v = (((const int*)m)[i] != 0) ? 1 : 0;
            else              v = (m[i] != 0) ? 1 : 0;
            g_maskb[i] = v;
        }
    } else if (bid <= 1024) {
        const int base = (bid - 1) * 2048;
        #pragma unroll
        for (int s = 0; s < 8; s++) {
            int idx = base + s * 256 + threadIdx.x;
            float2 v = ((const float2*)x)[idx];
            ((unsigned*)g_xf)[idx] = pack_h2(v.x, v.y);
        }
    } else {
        const int base = (bid - 1025) * 2048;
        const int total1 = 256 * QKV_COLS;
        #pragma unroll
        for (int s = 0; s < 8; s++) {
            int idx = base + s * 256 + threadIdx.x;
            if (idx < total1) {
                int kp = idx / QKV_COLS, n = idx % QKV_COLS;
                float a, b;
                if (n < 512) {
                    a = Wq[(2 * kp) * 512 + n] * SCALE;
                    b = Wq[(2 * kp + 1) * 512 + n] * SCALE;
                } else {
                    int nn = n - 512;
                    a = Wkv[(2 * kp) * 1024 + nn];
                    b = Wkv[(2 * kp + 1) * 1024 + nn];
                }
                size_t off = (size_t)n * 256 + kp;
                unsigned hp = pack_h2(a, b);
                float2 hf = __half22float2(*(__half2*)&hp);
                unsigned lp = pack_h2(a - hf.x, b - hf.y);   // residual (fp16 subnormal range)
                g_wqh[off] = hp;
                g_wql[off] = lp;
            } else {
                int j = idx - total1;
                int kp = j / DOUT, n = j % DOUT;
                float a = Wout[(2 * kp) * DOUT + n];
                float b = Wout[(2 * kp + 1) * DOUT + n];
                ((unsigned*)g_woutf)[(size_t)n * 256 + kp] = pack_h2(a, b);
            }
        }
    }
}

// =====================================================================
// k_transpose: bias transpose + mask, 2 i-rows/CTA, STANDALONE at occ 5
// (smem 40KB, ~40 regs -> 5 CTAs/SM; inside the old fat kernel this
// DRAM-latency-bound code was pinned to occ 3 by the GEMM's envelope).
// fp16 staging + PRMT emit, value-identical.
// =====================================================================
__global__ __launch_bounds__(256, 5) void k_transpose(const float* __restrict__ bias) {
    extern __shared__ unsigned s32[];                    // 2 x 1024*5 u32 = 40KB
    const int tid = threadIdx.x;
    const int bi2 = blockIdx.x;                          // 0..4095 (i-row pair)
    const int row0 = 2 * bi2;
    const int b = row0 >> 10;
    const int i0 = row0 & (NN - 1);
    const float* src = bias + (size_t)row0 * (NN * HH);

    // mask bytes once (same j indices for both rows)
    unsigned char mreg[8];
    #pragma unroll
    for (int sIt = 0; sIt < 8; sIt++) {
        int idx = tid + sIt * 256;
        mreg[sIt] = g_maskb[b * NN + (idx >> 1)];
    }

    #pragma unroll
    for (int r2 = 0; r2 < 2; r2++) {
        const float* srcr = src + (size_t)r2 * (NN * HH);
        unsigned* s32r = s32 + r2 * (NN * 5);
        #pragma unroll
        for (int sIt = 0; sIt < 8; sIt++) {
            int idx = tid + sIt * 256;                   // float4 index
            float4 v = *(const float4*)(srcr + idx * 4);
            int j = idx >> 1;
            int hg = idx & 1;
            unsigned char mb = mreg[sIt];
            float f0 = mb ? v.x : -60000.0f;
            float f1 = mb ? v.y : -60000.0f;
            float f2 = mb ? v.z : -60000.0f;
            float f3 = mb ? v.w : -60000.0f;
            int base = j * 5 + hg * 2;
            s32r[base] = pack_h2(f0, f1);
            s32r[base + 1] = pack_h2(f2, f3);
        }
    }
    __syncthreads();

    #pragma unroll
    for (int h = 0; h < HH; h++) {
        const int wI = h >> 1;
        const unsigned sel = (h & 1) ? 0x7632u : 0x5410u;
        #pragma unroll
        for (int r2 = 0; r2 < 2; r2++) {
            __half* dst = g_bias_h + (((size_t)(b * HH + h)) * NN + i0 + r2) * NN;
            const unsigned* s32r = s32 + r2 * (NN * 5);
            #pragma unroll
            for (int r = 0; r < 2; r++) {
                int j2 = tid + r * 256;                  // j-pair index
                unsigned w0 = s32r[(2 * j2) * 5 + wI];
                unsigned w1 = s32r[(2 * j2 + 1) * 5 + wI];
                *(unsigned*)(dst + 2 * j2) = __byte_perm(w0, w1, sel);
            }
        }
    }
}

// =====================================================================
// QKV GEMM, fp16 A + fp16 hi/lo W (2-mma): tile 128x64, 2-stage cp.async.
// Standalone kernel at occ 3.
// =====================================================================
#define AS2 40     // half stride (80B) for smem rows
#define GEMMQ_SMEM ((2*128*AS2 + 2*2*64*AS2) * 2)   // 40960 bytes

__global__ __launch_bounds__(256, 3) void k_gemm_qkv(int dummy) {
    extern __shared__ __half smh2[];
    __half* sA = smh2;                       // 2 stages x 128*AS2
    __half* sBh = sA + 2 * 128 * AS2;        // 2 stages x 64*AS2
    __half* sBl = sBh + 2 * 64 * AS2;        // 2 stages x 64*AS2

    const int cbid = blockIdx.x;
    const int tid = threadIdx.x, lane = tid & 31, warp = tid >> 5;
    const int g = lane >> 2, t = lane & 3;
    const int cb = (cbid % (QKV_COLS / 64)) * 64;
    const int rb = (cbid / (QKV_COLS / 64)) * 128;
    const int m0 = warp * 16;

    const __half* Bh = (const __half*)g_wqh;
    const __half* Bl = (const __half*)g_wql;

    const int ar = tid >> 2, ac8 = (tid & 3) * 8;
    const int br = tid >> 2, bc8 = (tid & 3) * 8;

    auto load_stage = [&](int st, int kt) {
        const int k0 = kt * 32;
        __half* pA = sA + st * 128 * AS2;
        #pragma unroll
        for (int sIt = 0; sIt < 2; sIt++) {
            int r = ar + sIt * 64;
            cp16(&pA[r * AS2 + ac8], g_xf + (size_t)(rb + r) * DIN + k0 + ac8);
        }
        size_t go = (size_t)(cb + br) * DIN + k0 + bc8;
        cp16(&sBh[st * 64 * AS2 + br * AS2 + bc8], Bh + go);
        cp16(&sBl[st * 64 * AS2 + br * AS2 + bc8], Bl + go);
    };

    const unsigned aoff = (unsigned)((m0 + (lane & 15)) * 80 + ((lane & 16) >> 4) * 16);
    const unsigned boff = (unsigned)(((lane & 7) + ((lane & 16) >> 1)) * 80 + ((lane & 8) >> 3) * 16);
    const unsigned sA_b = (unsigned)__cvta_generic_to_shared(sA);
    const unsigned sBh_b = (unsigned)__cvta_generic_to_shared(sBh);
    const unsigned sBl_b = (unsigned)__cvta_generic_to_shared(sBl);

    float acc[8][4];
    #pragma unroll
    for (int i = 0; i < 8; i++)
        #pragma unroll
        for (int j = 0; j < 4; j++) acc[i][j] = 0.f;

    load_stage(0, 0);
    CP_COMMIT;

    for (int kt = 0; kt < 16; kt++) {
        CP_WAIT0;
        __syncthreads();
        if (kt < 15) { load_stage((kt + 1) & 1, kt + 1); CP_COMMIT; }

        const unsigned stA = (kt & 1) * 128 * AS2 * 2;
        const unsigned stB = (kt & 1) * 64 * AS2 * 2;

        #pragma unroll
        for (int kc = 0; kc < 2; kc++) {
            const unsigned ko = kc * 32;
            unsigned a0, a1, a2, a3;
            ldsm4(a0, a1, a2, a3, sA_b + stA + aoff + ko);
            #pragma unroll
            for (int nbp = 0; nbp < 4; nbp++) {
                const unsigned bo = boff + (unsigned)(nbp * 16 * 80) + ko;
                unsigned bh0, bh1, bh2, bh3, bl0, bl1, bl2, bl3;
                ldsm4(bh0, bh1, bh2, bh3, sBh_b + stB + bo);
                ldsm4(bl0, bl1, bl2, bl3, sBl_b + stB + bo);
                float* A0 = acc[2 * nbp];
                float* A1 = acc[2 * nbp + 1];
                mma16f(A0[0], A0[1], A0[2], A0[3], a0, a1, a2, a3, bh0, bh1);
                mma16f(A0[0], A0[1], A0[2], A0[3], a0, a1, a2, a3, bl0, bl1);
                mma16f(A1[0], A1[1], A1[2], A1[3], a0, a1, a2, a3, bh2, bh3);
                mma16f(A1[0], A1[1], A1[2], A1[3], a0, a1, a2, a3, bl2, bl3);
            }
        }
        __syncthreads();
    }

    if (cb < 1024) {
        #pragma unroll
        for (int nb = 0; nb < 8; nb++) {
            int col = cb + nb * 8 + 2 * t;
            int r0 = rb + m0 + g;
            int r1 = r0 + 8;
            *(__half2*)(g_qk + (size_t)r0 * QKCOLS + col) = __floats2half2_rn(acc[nb][0], acc[nb][1]);
            *(__half2*)(g_qk + (size_t)r1 * QKCOLS + col) = __floats2half2_rn(acc[nb][2], acc[nb][3]);
        }
    } else {
        int h = (cb - 1024) >> 6;
        int r0 = rb + m0 + g;
        int b = r0 >> 10, n = r0 & 1023;
        __half* vt = g_vTh + (size_t)(b * 8 + h) * 64 * NN;
        #pragma unroll
        for (int nb = 0; nb < 8; nb++) {
            int d = nb * 8 + 2 * t;
            vt[(size_t)d * NN + n] = __float2half_rn(acc[nb][0]);
            vt[(size_t)(d + 1) * NN + n] = __float2half_rn(acc[nb][1]);
            vt[(size_t)d * NN + n + 8] = __float2half_rn(acc[nb][2]);
            vt[(size_t)(d + 1) * NN + n + 8] = __float2half_rn(acc[nb][3]);
        }
    }
    (void)dummy;
}

// =====================================================================
// out-proj GEMM, plain fp16, tile 128x128, 3-STAGE cp.async ring
// (prefetch distance 2 covers the full DRAM latency).
// =====================================================================
#define GEMM3_SMEM (3 * (128*AS2 + 128*AS2) * 2)   // 61440 bytes
__global__ __launch_bounds__(256, 2) void k_gemm_out(const float* __restrict__ bout,
                                                     float* __restrict__ Cout) {
    extern __shared__ __half smh2[];
    __half* sA = smh2;                       // 3 stages x 128*AS2
    __half* sB = sA + 3 * 128 * AS2;         // 3 stages x 128*AS2

    const int tid = threadIdx.x, lane = tid & 31, warp = tid >> 5;
    const int g = lane >> 2, t = lane & 3;
    const int cb = (blockIdx.x & 3) * 128;
    const int rb = (blockIdx.x >> 2) * 128;
    const int m0 = warp * 16;

    const int ar = tid >> 2, ac8 = (tid & 3) * 8;
    const int br = tid >> 2, bc8 = (tid & 3) * 8;

    auto load_stage = [&](int st, int kt) {
        const int k0 = kt * 32;
        __half* pA = sA + st * 128 * AS2;
        __half* pB = sB + st * 128 * AS2;
        #pragma unroll
        for (int sIt = 0; sIt < 2; sIt++) {
            int r = ar + sIt * 64;
            cp16(&pA[r * AS2 + ac8], g_attf + (size_t)(rb + r) * INNER + k0 + ac8);
            cp16(&pB[r * AS2 + bc8], g_woutf + (size_t)(cb + r) * INNER + k0 + bc8);
        }
    };

    const unsigned aoff = (unsigned)((m0 + (lane & 15)) * 80 + ((lane & 16) >> 4) * 16);
    const unsigned boff = (unsigned)(((lane & 7) + ((lane & 16) >> 1)) * 80 + ((lane & 8) >> 3) * 16);
    const unsigned sA_b = (unsigned)__cvta_generic_to_shared(sA);
    const unsigned sB_b = (unsigned)__cvta_generic_to_shared(sB);

    float acc[16][4];
    #pragma unroll
    for (int i = 0; i < 16; i++)
        #pragma unroll
        for (int j = 0; j < 4; j++) acc[i][j] = 0.f;

    load_stage(0, 0);
    CP_COMMIT;
    load_stage(1, 1);
    CP_COMMIT;

    for (int kt = 0; kt < 16; kt++) {
        CP_WAIT1;                       // group kt complete (kt+1 may be in flight)
        __syncthreads();                // kt data visible; stage (kt+2)%3 free
        if (kt < 14) { load_stage((kt + 2) % 3, kt + 2); CP_COMMIT; }

        const int st = kt % 3;
        const unsigned stA = (unsigned)(st * 128 * AS2 * 2);
        const unsigned stB = (unsigned)(st * 128 * AS2 * 2);

        #pragma unroll
        for (int kc = 0; kc < 2; kc++) {
            const unsigned ko = kc * 32;
            unsigned a0, a1, a2, a3;
            ldsm4(a0, a1, a2, a3, sA_b + stA + aoff + ko);
            #pragma unroll
            for (int nbp = 0; nbp < 8; nbp++) {
                unsigned b0, b1, c0, c1;
                ldsm4(b0, b1, c0, c1, sB_b + stB + boff + (unsigned)(nbp * 16 * 80) + ko);
                float* A0 = acc[2 * nbp];
                float* A1 = acc[2 * nbp + 1];
                mma16f(A0[0], A0[1], A0[2], A0[3], a0, a1, a2, a3, b0, b1);
                mma16f(A1[0], A1[1], A1[2], A1[3], a0, a1, a2, a3, c0, c1);
            }
        }
        __syncthreads();
    }

    #pragma unroll
    for (int nb = 0; nb < 16; nb++) {
        int col = cb + nb * 8 + 2 * t;
        float b0v = bout[col], b1v = bout[col + 1];
        int r0 = rb + m0 + g;
        int r1 = r0 + 8;
        *(float2*)(Cout + (size_t)r0 * DOUT + col) = make_float2(acc[nb][0] + b0v, acc[nb][1] + b1v);
        *(float2*)(Cout + (size_t)r1 * DOUT + col) = make_float2(acc[nb][2] + b0v, acc[nb][3] + b1v);
    }
}

// =====================================================================
// Flash attention: fp16 tiles, f16x2 ex2 softmax, ones-B row sums,
// per-warp bias staging, occ 3 (unchanged).
// =====================================================================
#define HS 72            // half stride per smem row (144B)
#define HSB 144
#define ONES16 0x3C003C00u
__global__ __launch_bounds__(256, 3) void k_flash() {
    extern __shared__ __half smh[];
    __half* Qs = smh;                     // 128*HS
    __half* Ks = Qs + 128 * HS;           // 64*HS  [token][d]
    __half* Vt = Ks + 64 * HS;            // 64*HS  [d][token]
    __half* Ps = Vt + 64 * HS;            // 128*HS (bias overlay + P)

    const int tid = threadIdx.x, lane = tid & 31, warp = tid >> 5;
    const int g = lane >> 2, t = lane & 3;
    const int it = blockIdx.x & 7;
    const int bh = blockIdx.x >> 3;
    const int b = bh >> 3, h = bh & 7;
    const int i0 = it * 128;
    const int m0 = warp * 16;
    const float NEG_INF = __int_as_float(0xff800000);

    const __half* qbase = g_qk + (size_t)b * NN * QKCOLS + h * 64;
    const __half* kbase = qbase + 512;
    const __half* vbase = g_vTh + (size_t)bh * 64 * NN;
    const __half* bbase = g_bias_h + ((size_t)bh * NN + i0) * NN;

    const unsigned aoff = (unsigned)((m0 + (lane & 15)) * HSB + ((lane & 16) >> 4) * 16);
    const unsigned boff = (unsigned)(((lane & 7) + ((lane & 16) >> 1)) * HSB + ((lane & 8) >> 3) * 16);
    const unsigned qs_b = (unsigned)__cvta_generic_to_shared(Qs);
    const unsigned ks_b = (unsigned)__cvta_generic_to_shared(Ks);
    const unsigned vt_b = (unsigned)__cvta_generic_to_shared(Vt);
    const unsigned ps_b = (unsigned)__cvta_generic_to_shared(Ps);

    // per-warp bias chunk coords: warp w owns rows m0..m0+15
    const int bw_r = m0 + (lane >> 3);
    const int bw_c8 = (lane & 7) * 8;

    // Q tile (own cp group)
    #pragma unroll
    for (int sIt = 0; sIt < 4; sIt++) {
        int idx = tid + sIt * 256;
        int r = idx >> 3, c8 = (idx & 7) * 8;
        cp16(&Qs[r * HS + c8], qbase + (size_t)(i0 + r) * QKCOLS + c8);
    }
    CP_COMMIT;

    float accO[8][4];
    #pragma unroll
    for (int i = 0; i < 8; i++)
        #pragma unroll
        for (int j = 0; j < 4; j++) accO[i][j] = 0.f;
    float mrow0 = NEG_INF, mrow1 = NEG_INF;
    float lrow0 = 0.f, lrow1 = 0.f;

    for (int jt = 0; jt < 16; jt++) {
        const int j0 = jt * 64;
        __syncthreads();                                   // buffers free (Ks/Vt/Ps)
        #pragma unroll
        for (int sIt = 0; sIt < 2; sIt++) {
            int idx = tid + sIt * 256;
            int r = idx >> 3, c8 = (idx & 7) * 8;
            cp16(&Ks[r * HS + c8], kbase + (size_t)(j0 + r) * QKCOLS + c8);
            cp16(&Vt[r * HS + c8], vbase + (size_t)r * NN + j0 + c8);
        }
        CP_COMMIT;                                         // group: K/V
        #pragma unroll
        for (int sIt = 0; sIt < 4; sIt++) {
            int r = bw_r + sIt * 4;
            cp16(&Ps[r * HS + bw_c8], bbase + (size_t)r * NN + j0 + bw_c8);
        }
        CP_COMMIT;                                         // group: bias (warp-local rows)
        CP_WAIT1;
        __syncthreads();                                   // K/V visible to all warps

        // S = Q @ K^T
        float s[8][4];
        #pragma unroll
        for (int i = 0; i < 8; i++)
            #pragma unroll
            for (int j = 0; j < 4; j++) s[i][j] = 0.f;
        #pragma unroll
        for (int kc = 0; kc < 4; kc++) {
            const unsigned ko = kc * 32;
            unsigned a0, a1, a2, a3;
            ldsm4(a0, a1, a2, a3, qs_b + aoff + ko);
            #pragma unroll
            for (int nbp = 0; nbp < 4; nbp++) {
                unsigned b0, b1, c0, c1;
                ldsm4(b0, b1, c0, c1, ks_b + boff + (unsigned)(nbp * 16 * HSB) + ko);
                float* S0 = s[2 * nbp];
                float* S1 = s[2 * nbp + 1];
                mma16f(S0[0], S0[1], S0[2], S0[3], a0, a1, a2, a3, b0, b1);
                mma16f(S1[0], S1[1], S1[2], S1[3], a0, a1, a2, a3, c0, c1);
            }
        }
        CP_WAIT0;                                          // this thread's bias chunks done
        __syncwarp();                                      // warp's own rows visible

        // + bias (fp16), row max
        float mx0 = NEG_INF, mx1 = NEG_INF;
        #pragma unroll
        for (int nb = 0; nb < 8; nb++) {
            int c = nb * 8 + 2 * t;
            float2 fA = __half22float2(*(__half2*)&Ps[(m0 + g) * HS + c]);
            float2 fB = __half22float2(*(__half2*)&Ps[(m0 + g + 8) * HS + c]);
            s[nb][0] += fA.x;
            s[nb][1] += fA.y;
            s[nb][2] += fB.x;
            s[nb][3] += fB.y;
            mx0 = fmaxf(mx0, fmaxf(s[nb][0], s[nb][1]));
            mx1 = fmaxf(mx1, fmaxf(s[nb][2], s[nb][3]));
        }
        mx0 = fmaxf(mx0, __shfl_xor_sync(0xffffffffu, mx0, 1));
        mx0 = fmaxf(mx0, __shfl_xor_sync(0xffffffffu, mx0, 2));
        mx1 = fmaxf(mx1, __shfl_xor_sync(0xffffffffu, mx1, 1));
        mx1 = fmaxf(mx1, __shfl_xor_sync(0xffffffffu, mx1, 2));

        float mn0 = fmaxf(mrow0, mx0), mn1 = fmaxf(mrow1, mx1);
        float al0 = ex2((mrow0 - mn0) * LOG2E);
        float al1 = ex2((mrow1 - mn1) * LOG2E);
        mrow0 = mn0;
        mrow1 = mn1;

        // P = exp(s - mn) via f16x2 ex2 -> stored directly as fp16 pairs
        #pragma unroll
        for (int nb = 0; nb < 8; nb++) {
            int c = nb * 8 + 2 * t;
            unsigned q01 = h2ex2(pack_h2((s[nb][0] - mn0) * LOG2E, (s[nb][1] - mn0) * LOG2E));
            unsigned q23 = h2ex2(pack_h2((s[nb][2] - mn1) * LOG2E, (s[nb][3] - mn1) * LOG2E));
            *(unsigned*)&Ps[(m0 + g) * HS + c] = q01;
            *(unsigned*)&Ps[(m0 + g + 8) * HS + c] = q23;
        }

        #pragma unroll
        for (int nb = 0; nb < 8; nb++) {
            accO[nb][0] *= al0;
            accO[nb][1] *= al0;
            accO[nb][2] *= al1;
            accO[nb][3] *= al1;
        }
        __syncwarp();                                      // P rows warp-private
        // O += P @ V ; row sums via ones-B mma
        float sacc0 = 0.f, sacc1 = 0.f, sacc2 = 0.f, sacc3 = 0.f;
        #pragma unroll
        for (int kc = 0; kc < 4; kc++) {
            const unsigned ko = kc * 32;
            unsigned a0, a1, a2, a3;
            ldsm4(a0, a1, a2, a3, ps_b + aoff + ko);
            mma16f(sacc0, sacc1, sacc2, sacc3, a0, a1, a2, a3, ONES16, ONES16);
            #pragma unroll
            for (int nbp = 0; nbp < 4; nbp++) {
                unsigned b0, b1, c0, c1;
                ldsm4(b0, b1, c0, c1, vt_b + boff + (unsigned)(nbp * 16 * HSB) + ko);
                float* O0 = accO[2 * nbp];
                float* O1 = accO[2 * nbp + 1];
                mma16f(O0[0], O0[1], O0[2], O0[3], a0, a1, a2, a3, b0, b1);
                mma16f(O1[0], O1[1], O1[2], O1[3], a0, a1, a2, a3, c0, c1);
            }
        }
        lrow0 = lrow0 * al0 + sacc0;
        lrow1 = lrow1 * al1 + sacc2;
    }

    // epilogue: normalize, store attention output as fp16
    float inv0 = 1.f / lrow0;
    float inv1 = 1.f / lrow1;
    __half* arow = g_attf + (size_t)h * 64;
    #pragma unroll
    for (int nb = 0; nb < 8; nb++) {
        int col = nb * 8 + 2 * t;
        int r0 = b * NN + i0 + m0 + g;
        int r1 = r0 + 8;
        *(__half2*)(arow + (size_t)r0 * INNER + col) =
            __floats2half2_rn(accO[nb][0] * inv0, accO[nb][1] * inv0);
        *(__half2*)(arow + (size_t)r1 * INNER + col) =
            __floats2half2_rn(accO[nb][2] * inv1, accO[nb][3] * inv1);
    }
}

// =====================================================================
extern "C" void kernel_launch(void* const* d_in, const int* in_sizes, int n_in,
                              void* d_out, int out_size) {
    (void)in_sizes; (void)n_in; (void)out_size;
    const float* x = (const float*)d_in[0];
    const unsigned char* mask = (const unsigned char*)d_in[1];
    const float* bias = (const float*)d_in[2];
    const float* Wq = (const float*)d_in[3];
    const float* Wkv = (const float*)d_in[4];
    const float* Wout = (const float*)d_in[5];
    const float* bout = (const float*)d_in[6];
    float* out = (float*)d_out;

    const int flash_smem = (128 + 64 + 64 + 128) * HS * 2;   // 55296
    const int trans_smem = 2 * NN * 5 * 4;                   // 40960
    cudaFuncSetAttribute(k_flash, cudaFuncAttributeMaxDynamicSharedMemorySize, flash_smem);
    cudaFuncSetAttribute(k_transpose, cudaFuncAttributeMaxDynamicSharedMemorySize, trans_smem);
    cudaFuncSetAttribute(k_gemm_qkv, cudaFuncAttributeMaxDynamicSharedMemorySize, GEMMQ_SMEM);
    cudaFuncSetAttribute(k_gemm_out, cudaFuncAttributeMaxDynamicSharedMemorySize, GEMM3_SMEM);

    k_prep<<<1281, 256>>>(mask, x, Wq, Wkv, Wout);
    k_transpose<<<4096, 256, trans_smem>>>(bias);
    k_gemm_qkv<<<(QKV_COLS / 64) * (NROWS / 128), 256, GEMMQ_SMEM>>>(0);
    k_flash<<<BB * HH * (NN / 128), 256, flash_smem>>>();
    k_gemm_out<<<(DOUT / 128) * (NROWS / 128), 256, GEMM3_SMEM>>>(bout, out);
}